// round 2
// baseline (speedup 1.0000x reference)
#include <cuda_runtime.h>
#include <cuda_bf16.h>

// Problem constants (FilterDetections: B=4, N=49104, C=90)
#define NB 4
#define NA 49104
#define NC 90
#define MAXDET 100
#define NEGV (-1e30f)
#define SCORE_THR 0.01f
#define IOU_THR 0.1f

#define T1 1024
#define IPT 48            // 48 * 1024 = 49152 >= 49104

#define T2 1024
#define TOT (NC * MAXDET) // 9000
#define IPT2 9            // 9 * 1024 = 9216 >= 9000

// Scratch: kept detections per (image, class)
__device__ float g_ks[NB * NC * MAXDET];
__device__ int   g_ka[NB * NC * MAXDET];
__device__ int   g_kc[NB * NC];

// ---------------------------------------------------------------------------
// Phase 1: greedy per-class NMS. One CTA per (b, c) pair.
// Scores live in registers (NEG sentinel = filtered/suppressed/selected).
// ---------------------------------------------------------------------------
__global__ __launch_bounds__(T1) void nms_kernel(const float* __restrict__ boxes,
                                                 const float* __restrict__ cls)
{
    const int pair = blockIdx.x;
    const int b = pair / NC;
    const int c = pair % NC;
    const float4* __restrict__ bb = (const float4*)(boxes + (size_t)b * NA * 4);
    const float* __restrict__ sc = cls + (size_t)b * NA * NC + c;
    const int t = threadIdx.x;

    // Load + threshold scores into registers
    float s[IPT];
#pragma unroll
    for (int i = 0; i < IPT; i++) {
        int a = i * T1 + t;
        float v = (a < NA) ? sc[(size_t)a * NC] : NEGV;
        s[i] = (v > SCORE_THR) ? v : NEGV;
    }

    __shared__ float wv[32];
    __shared__ int   wi[32];
    __shared__ float sbox[4];
    __shared__ int   ssel;
    __shared__ float ks_s[MAXDET];
    __shared__ int   ka_s[MAXDET];
    __shared__ int   scnt;
    if (t == 0) scnt = 0;

    bool exhausted = false;

    for (int it = 0; it < MAXDET; it++) {
        // ---- local argmax (ties -> lowest anchor index, matching jnp.argmax)
        float bv = NEGV;
        int   bi = 0x7FFFFFFF;
#pragma unroll
        for (int i = 0; i < IPT; i++) {
            if (s[i] > bv) { bv = s[i]; bi = i * T1 + t; }
        }
        // ---- warp reduce
#pragma unroll
        for (int o = 16; o; o >>= 1) {
            float ov = __shfl_down_sync(0xffffffffu, bv, o);
            int   oi = __shfl_down_sync(0xffffffffu, bi, o);
            if (ov > bv || (ov == bv && oi < bi)) { bv = ov; bi = oi; }
        }
        if ((t & 31) == 0) { wv[t >> 5] = bv; wi[t >> 5] = bi; }
        __syncthreads();
        // ---- block reduce (warp 0)
        if (t < 32) {
            bv = wv[t]; bi = wi[t];
#pragma unroll
            for (int o = 16; o; o >>= 1) {
                float ov = __shfl_down_sync(0xffffffffu, bv, o);
                int   oi = __shfl_down_sync(0xffffffffu, bi, o);
                if (ov > bv || (ov == bv && oi < bi)) { bv = ov; bi = oi; }
            }
            if (t == 0) {
                if (bv > -0.5e30f) {
                    float4 bx = bb[bi];
                    sbox[0] = bx.x; sbox[1] = bx.y; sbox[2] = bx.z; sbox[3] = bx.w;
                    ssel = bi;
                    int k = scnt;
                    ks_s[k] = bv;
                    ka_s[k] = bi;
                    scnt = k + 1;
                } else {
                    ssel = -1;
                }
            }
        }
        __syncthreads();

        int sel = ssel;
        if (sel < 0) { exhausted = true; break; }

        // ---- suppression pass: IOU of selected box vs all still-active anchors
        float y1 = sbox[0], x1 = sbox[1], y2 = sbox[2], x2 = sbox[3];
        float sarea = (y2 - y1) * (x2 - x1);
#pragma unroll
        for (int i = 0; i < IPT; i++) {
            if (s[i] > -1e29f) {
                int a = i * T1 + t;
                float4 bx = bb[a];
                float iy1 = fmaxf(y1, bx.x);
                float ix1 = fmaxf(x1, bx.y);
                float iy2 = fminf(y2, bx.z);
                float ix2 = fminf(x2, bx.w);
                float inter = fmaxf(iy2 - iy1, 0.0f) * fmaxf(ix2 - ix1, 0.0f);
                float barea = (bx.z - bx.x) * (bx.w - bx.y);
                float iou = inter / (sarea + barea - inter + 1e-8f);
                if (iou > IOU_THR) s[i] = NEGV;
                if (a == sel)      s[i] = NEGV;  // selected always cleared
            }
        }
        __syncthreads();  // protect sbox/ssel/wv for next iteration
    }

    __syncthreads();
    if (t == 0) {
        int cnt = scnt;
        // Reference quirk: after exhaustion, jnp.argmax over all-NEG returns 0
        // and keep.at[0].set(False) un-keeps anchor 0 if it was selected.
        if (exhausted) {
            for (int k = 0; k < cnt; k++) {
                if (ka_s[k] == 0) {
                    cnt--;
                    ks_s[k] = ks_s[cnt];
                    ka_s[k] = ka_s[cnt];
                    break;
                }
            }
            scnt = cnt;
        }
    }
    __syncthreads();
    int cnt = scnt;
    int base = pair * MAXDET;
    if (t < cnt) {
        g_ks[base + t] = ks_s[t];
        g_ka[base + t] = ka_s[t];
    }
    if (t == 0) g_kc[pair] = cnt;
}

// ---------------------------------------------------------------------------
// Phase 2: per-image top-100 over all kept (anchor, class) detections.
// Matches jax.lax.top_k tie-break: value desc, flat index (anchor*C+c) asc.
// One CTA per image; candidate values live in registers.
// ---------------------------------------------------------------------------
__global__ __launch_bounds__(T2) void topk_kernel(const float* __restrict__ boxes,
                                                  float* __restrict__ out)
{
    const int b = blockIdx.x;
    const int t = threadIdx.x;

    __shared__ int cnts[NC];
    if (t < NC) cnts[t] = g_kc[b * NC + t];
    __syncthreads();

    // Load candidates into registers
    float val[IPT2];
    int   flt[IPT2];
#pragma unroll
    for (int i = 0; i < IPT2; i++) {
        int slot = i * T2 + t;
        val[i] = NEGV;
        flt[i] = 0x7FFFFFFF;
        if (slot < TOT) {
            int c = slot / MAXDET;
            int j = slot % MAXDET;
            if (j < cnts[c]) {
                val[i] = g_ks[(size_t)b * TOT + slot];
                flt[i] = g_ka[(size_t)b * TOT + slot] * NC + c;
            }
        }
    }

    __shared__ float wv[32];
    __shared__ int   wf[32];
    __shared__ int   ws[32];
    __shared__ int   bslot_sh;

    const float4* __restrict__ bb = (const float4*)(boxes + (size_t)b * NA * 4);
    float* ob = out + (size_t)b * MAXDET * 4;
    float* os = out + (size_t)NB * MAXDET * 4 + (size_t)b * MAXDET;
    float* ol = out + (size_t)NB * MAXDET * 5 + (size_t)b * MAXDET;

    for (int k = 0; k < MAXDET; k++) {
        float bv = NEGV;
        int   bf = 0x7FFFFFFF;
        int   bs = -1;
#pragma unroll
        for (int i = 0; i < IPT2; i++) {
            if (val[i] > bv || (val[i] == bv && flt[i] < bf)) {
                bv = val[i]; bf = flt[i]; bs = i * T2 + t;
            }
        }
#pragma unroll
        for (int o = 16; o; o >>= 1) {
            float ov = __shfl_down_sync(0xffffffffu, bv, o);
            int   of = __shfl_down_sync(0xffffffffu, bf, o);
            int   osl = __shfl_down_sync(0xffffffffu, bs, o);
            if (ov > bv || (ov == bv && of < bf)) { bv = ov; bf = of; bs = osl; }
        }
        if ((t & 31) == 0) { wv[t >> 5] = bv; wf[t >> 5] = bf; ws[t >> 5] = bs; }
        __syncthreads();
        if (t < 32) {
            bv = wv[t]; bf = wf[t]; bs = ws[t];
#pragma unroll
            for (int o = 16; o; o >>= 1) {
                float ov = __shfl_down_sync(0xffffffffu, bv, o);
                int   of = __shfl_down_sync(0xffffffffu, bf, o);
                int   osl = __shfl_down_sync(0xffffffffu, bs, o);
                if (ov > bv || (ov == bv && of < bf)) { bv = ov; bf = of; bs = osl; }
            }
            if (t == 0) {
                if (bv > -0.5e30f) {
                    int anchor = bf / NC;
                    int lab = bf - anchor * NC;
                    float4 bx = bb[anchor];
                    ob[k * 4 + 0] = bx.x;
                    ob[k * 4 + 1] = bx.y;
                    ob[k * 4 + 2] = bx.z;
                    ob[k * 4 + 3] = bx.w;
                    os[k] = bv;
                    ol[k] = (float)lab;
                    bslot_sh = bs;
                } else {
                    ob[k * 4 + 0] = -1.0f;
                    ob[k * 4 + 1] = -1.0f;
                    ob[k * 4 + 2] = -1.0f;
                    ob[k * 4 + 3] = -1.0f;
                    os[k] = -1.0f;
                    ol[k] = -1.0f;
                    bslot_sh = -1;
                }
            }
        }
        __syncthreads();
        int bsel = bslot_sh;
        if (bsel >= 0) {
            // Owner thread clears its selected slot
            if ((bsel & (T2 - 1)) == t) {
                int i = bsel >> 10;  // T2 = 1024
#pragma unroll
                for (int ii = 0; ii < IPT2; ii++) {
                    if (ii == i) { val[ii] = NEGV; flt[ii] = 0x7FFFFFFF; }
                }
            }
        }
        __syncthreads();
    }
}

extern "C" void kernel_launch(void* const* d_in, const int* in_sizes, int n_in,
                              void* d_out, int out_size)
{
    const float* boxes = (const float*)d_in[0];
    const float* cls   = (const float*)d_in[1];
    float* out = (float*)d_out;

    nms_kernel<<<NB * NC, T1>>>(boxes, cls);
    topk_kernel<<<NB, T2>>>(boxes, out);
}